// round 8
// baseline (speedup 1.0000x reference)
#include <cuda_runtime.h>
#include <cstdint>

#define NHID    512
#define KQROW   128            // 16B units per 512-float row
#define NKQ     4              // 16B units per chunk per row (16 floats)
#define NCHUNK  32             // KQROW / NKQ
#define NBUF    4              // cp.async pipeline depth (3-chunk lookahead)
#define SLOT    257            // 16B slots per kq-plane (>=250 rows + pad)
#define NCLS    250
#define WROWS   200
#define OUTW    450
#define TGC     16             // tokens per cls CTA
#define MAXTOK  2048

#define SW_BYTES (NBUF * NKQ * SLOT * 16)          // 65792
#define SX_OFF   SW_BYTES
#define SMEM_DYN (SW_BYTES + 16 * NHID * 4)        // + 32768 = 98560

extern __shared__ char dynsmem[];

// ---- packed fp32x2 helpers (FFMA2 only reachable via PTX on sm_103a) ----
__device__ __forceinline__ void fma2(unsigned long long& acc,
                                     unsigned long long a,
                                     unsigned long long b) {
    asm("fma.rn.f32x2 %0, %1, %2, %0;" : "+l"(acc) : "l"(a), "l"(b));
}
__device__ __forceinline__ float2 u2f(unsigned long long v) {
    float2 f;
    asm("mov.b64 {%0, %1}, %2;" : "=f"(f.x), "=f"(f.y) : "l"(v));
    return f;
}

// ---- cp.async primitives ----
__device__ __forceinline__ uint32_t smem_u32(const void* p) {
    uint32_t a;
    asm("{ .reg .u64 t; cvta.to.shared.u64 t, %1; cvt.u32.u64 %0, t; }"
        : "=r"(a) : "l"(p));
    return a;
}
__device__ __forceinline__ void cpa16(uint32_t dst, const void* src) {
    asm volatile("cp.async.ca.shared.global [%0], [%1], 16;\n"
                 :: "r"(dst), "l"(src));
}
__device__ __forceinline__ void cpa_commit() {
    asm volatile("cp.async.commit_group;\n");
}
template <int N>
__device__ __forceinline__ void cpa_wait() {
    asm volatile("cp.async.wait_group %0;\n" :: "n"(N));
}

// ---- stage one W k-chunk (ck) into ring buffer slot buf, transposed ----
// gmem W row-major [nrows][512 f32]; smem layout [buf][kq][row] of 16B units.
__device__ __forceinline__ void stage_w_chunk(uint32_t sw_u32, const char* Wg,
                                              int nrows, int ck, int buf,
                                              int tid) {
    const char* src = Wg + (size_t)ck * NKQ * 16;
    const uint32_t dstb = sw_u32 + buf * (NKQ * SLOT * 16);
    for (int idx = tid; idx < nrows * NKQ; idx += 256) {
        int row = idx >> 2, kq = idx & 3;
        cpa16(dstb + (uint32_t)(kq * SLOT + row) * 16,
              src + (size_t)row * (NHID * 4) + kq * 16);
    }
}

// ---- stage T tokens' x rows (padded with last valid token) ----
__device__ __forceinline__ void stage_x(uint32_t sx_u32, const float* xg,
                                        const int* s_tok, int t0, int lim,
                                        int T, int tid) {
    for (int idx = tid; idx < T * KQROW; idx += 256) {
        int t = idx >> 7, u = idx & 127;
        int tt = t0 + t; if (tt >= lim) tt = lim - 1;
        int tok = s_tok ? s_tok[tt] : tt;
        cpa16(sx_u32 + (uint32_t)idx * 16,
              (const char*)xg + ((size_t)tok * KQROW + u) * 16);
    }
}

// ---- one GEMM pass: thread tid owns row tid (tid < nrows), T tokens ----
// Caller has committed one async group staging x for tokens [t0, t0+T).
template <int T>
__device__ void gemm_pass(const char* Wg, int nrows, const float* bias,
                          const int* s_tok, int t0, int lim,
                          float* __restrict__ out, int colbase, int tid) {
    const uint32_t sw_u32 = smem_u32(dynsmem);
    unsigned long long A[T];
#pragma unroll
    for (int t = 0; t < T; t++) A[t] = 0ull;

#pragma unroll
    for (int p = 0; p < NBUF - 1; p++) {
        stage_w_chunk(sw_u32, Wg, nrows, p, p, tid);
        cpa_commit();
    }

    const ulonglong2* xu = (const ulonglong2*)(dynsmem + SX_OFF);
    const bool active = tid < nrows;

#pragma unroll 1
    for (int ck = 0; ck < NCHUNK; ck++) {
        cpa_wait<NBUF - 2>();   // chunk ck's group (and x on first iter) done
        __syncthreads();        // all threads' copies visible
        const int b = ck & (NBUF - 1);
        if (active) {
#pragma unroll
            for (int kq = 0; kq < NKQ; kq++) {
                ulonglong2 w = *(const ulonglong2*)(
                    dynsmem + (size_t)((b * NKQ + kq) * SLOT + tid) * 16);
                const ulonglong2* xq = xu + (ck * NKQ + kq);
#pragma unroll
                for (int t = 0; t < T; t++) {
                    ulonglong2 xv = xq[t * KQROW];   // uniform broadcast LDS
                    fma2(A[t], w.x, xv.x);
                    fma2(A[t], w.y, xv.y);
                }
            }
        }
        const int nk = ck + NBUF - 1;
        if (nk < NCHUNK)
            stage_w_chunk(sw_u32, Wg, nrows, nk, nk & (NBUF - 1), tid);
        cpa_commit();           // uniform commit cadence (may be empty)
    }

    if (active) {
        const float bi = bias[tid];
#pragma unroll
        for (int t = 0; t < T; t++) {
            if (t0 + t < lim) {
                float2 f = u2f(A[t]);
                int tok = s_tok ? s_tok[t0 + t] : (t0 + t);
                out[(size_t)tok * OUTW + colbase + tid] = f.x + f.y + bi;
            }
        }
    }
    __syncthreads();   // protect s_x / s_w before caller's next staging
}

__global__ __launch_bounds__(256, 2)
void decoder_kernel(const float* __restrict__ x,
                    const float* __restrict__ Wc,
                    const float* __restrict__ bc,
                    const float* __restrict__ Ww,
                    const float* __restrict__ bw,
                    const int* __restrict__ cls_raw,
                    float* __restrict__ out, int n) {
    __shared__ int s_tok[MAXTOK];
    __shared__ int s_cnt, s_not64;
    const int tid = threadIdx.x;
    const int bi = blockIdx.x;
    const uint32_t sx_u32 = smem_u32(dynsmem) + SX_OFF;

    if (bi < NCLS) {
        // ----------------- words part: one class per CTA -----------------
        const int c = bi;
        if (tid == 0) { s_cnt = 0; s_not64 = 0; }
        __syncthreads();
        // int32 vs int64 detection: odd int32 slots of int64 values in
        // [0,250) are all zero; int32 class values are not all zero.
        int flag = 0;
        for (int j = 2 * tid + 1; j < n; j += 512)
            if (cls_raw[j] != 0) flag = 1;
        if (flag) s_not64 = 1;
        __syncthreads();
        const int is64 = !s_not64;
        for (int i = tid; i < n; i += 256) {
            int cc = is64 ? cls_raw[2 * i] : cls_raw[i];
            if (cc == c) {
                int p = atomicAdd(&s_cnt, 1);
                if (p < MAXTOK) s_tok[p] = i;
            }
        }
        __syncthreads();
        const int cnt = min(s_cnt, MAXTOK);
        if (cnt == 0) return;

        const char* Wg = (const char*)Ww + (size_t)c * WROWS * NHID * 4;
        const float* biasw = bw + (size_t)c * WROWS;

        int t0 = 0;
        while (t0 < cnt) {
            const int rem = cnt - t0;
            if (rem >= 13) {
                stage_x(sx_u32, x, s_tok, t0, cnt, 16, tid); cpa_commit();
                gemm_pass<16>(Wg, WROWS, biasw, s_tok, t0, cnt, out, NCLS, tid);
                t0 += 16;
            } else if (rem >= 9) {
                stage_x(sx_u32, x, s_tok, t0, cnt, 12, tid); cpa_commit();
                gemm_pass<12>(Wg, WROWS, biasw, s_tok, t0, cnt, out, NCLS, tid);
                t0 += 12;
            } else if (rem >= 5) {
                stage_x(sx_u32, x, s_tok, t0, cnt, 8, tid); cpa_commit();
                gemm_pass<8>(Wg, WROWS, biasw, s_tok, t0, cnt, out, NCLS, tid);
                t0 += 8;
            } else {
                stage_x(sx_u32, x, s_tok, t0, cnt, 4, tid); cpa_commit();
                gemm_pass<4>(Wg, WROWS, biasw, s_tok, t0, cnt, out, NCLS, tid);
                t0 += 4;
            }
        }
    } else {
        // ----------------- cls part: 16 tokens per CTA -----------------
        const int g = bi - NCLS;
        const int t0 = g * TGC;
        if (t0 >= n) return;
        stage_x(sx_u32, x, nullptr, t0, n, TGC, tid); cpa_commit();
        gemm_pass<TGC>((const char*)Wc, NCLS, bc, nullptr, t0, n, out, 0, tid);
    }
}

extern "C" void kernel_launch(void* const* d_in, const int* in_sizes, int n_in,
                              void* d_out, int out_size) {
    const float* x  = (const float*)d_in[0];
    const float* Wc = (const float*)d_in[1];
    const float* bc = (const float*)d_in[2];
    const float* Ww = (const float*)d_in[3];
    const float* bw = (const float*)d_in[4];
    const int*   ci = (const int*)d_in[5];
    const int n = in_sizes[0] / NHID;
    float* out = (float*)d_out;

    cudaFuncSetAttribute(decoder_kernel,
                         cudaFuncAttributeMaxDynamicSharedMemorySize, SMEM_DYN);
    const int grid = NCLS + (n + TGC - 1) / TGC;
    decoder_kernel<<<grid, 256, SMEM_DYN>>>(x, Wc, bc, Ww, bw, ci, out, n);
}

// round 11
// speedup vs baseline: 1.0764x; 1.0764x over previous
#include <cuda_runtime.h>
#include <cstdint>

#define NHID    512
#define NCLS    250
#define WROWS   200
#define OUTW    450
#define MAXTOK  2048
#define NS      8                     // k-slices per row (64 floats each)
#define SLB     272                   // 256B slice + 16B pad
#define ROWB    (NS * SLB)            // 2176 bytes per staged row
#define CR      10                    // weight rows per staged chunk
#define BUFBYTES (CR * ROWB)          // 21760
#define SMEM_DYN (2 * BUFBYTES)       // 43520

extern __shared__ __align__(16) char dynsmem[];

// ---- packed fp32x2 FMA (FFMA2): PTX-only on sm_103a, 2x FFMA throughput ----
__device__ __forceinline__ void fma2(unsigned long long& acc,
                                     unsigned long long a,
                                     unsigned long long b) {
    asm("fma.rn.f32x2 %0, %1, %2, %0;" : "+l"(acc) : "l"(a), "l"(b));
}
__device__ __forceinline__ float2 u2f(unsigned long long v) {
    float2 f;
    asm("mov.b64 {%0, %1}, %2;" : "=f"(f.x), "=f"(f.y) : "l"(v));
    return f;
}

// ---- cp.async primitives ----
__device__ __forceinline__ uint32_t smem_u32(const void* p) {
    uint32_t a;
    asm("{ .reg .u64 t; cvta.to.shared.u64 t, %1; cvt.u32.u64 %0, t; }"
        : "=r"(a) : "l"(p));
    return a;
}
__device__ __forceinline__ void cpa16(uint32_t dst, const void* src) {
    asm volatile("cp.async.ca.shared.global [%0], [%1], 16;\n"
                 :: "r"(dst), "l"(src));
}
__device__ __forceinline__ void cpa_commit() {
    asm volatile("cp.async.commit_group;\n");
}
template <int N>
__device__ __forceinline__ void cpa_wait() {
    asm volatile("cp.async.wait_group %0;\n" :: "n"(N));
}

// ---- stage weight chunk c: rows [c*CR, c*CR+cr) of W (row = 2KB) ----
// smem layout: row r -> 8 k-slices of 256B at r*ROWB + slice*SLB.
__device__ __forceinline__ void stage_chunk(uint32_t sbase, const char* W,
                                            int c, int nrows, int tid) {
    const int r0 = c * CR;
    const int cr = min(CR, nrows - r0);
    const uint32_t dst0 = sbase + (uint32_t)(c & 1) * BUFBYTES;
    for (int idx = tid; idx < cr * 128; idx += 128) {
        int row = idx >> 7, u = idx & 127;          // u = 16B unit in row
        cpa16(dst0 + (uint32_t)(row * ROWB + (u >> 4) * SLB + (u & 15) * 16),
              W + (size_t)(r0 + row) * 2048 + (size_t)u * 16);
    }
}

// ---- sweep rows [0, nrows) of W for this warp's 4 register-resident tokens.
// Lane = (ks = lane>>2 k-slice of 64 floats, tq = lane&3 token). Warp handles
// rows (r % nsh) == myidx within each chunk. All threads participate in
// staging/barriers (uniform control flow).
__device__ void sweep(const char* W, const float* __restrict__ bias,
                      int nrows, int colbase,
                      const ulonglong2* xr2,      // [16] = 64 floats, in regs
                      int my_tok, bool valid, int nsh, int myidx,
                      float* __restrict__ out,
                      int tid, int lane, int ks) {
    const uint32_t sbase = smem_u32(dynsmem);
    const int nc = (nrows + CR - 1) / CR;

    stage_chunk(sbase, W, 0, nrows, tid);
    cpa_commit();
    if (nc > 1) { stage_chunk(sbase, W, 1, nrows, tid); }
    cpa_commit();

    for (int c = 0; c < nc; c++) {
        cpa_wait<1>();          // chunk c's group complete (commit-ordered)
        __syncthreads();
        const int cr = min(CR, nrows - c * CR);
        const char* wb = dynsmem + (c & 1) * BUFBYTES + ks * SLB;
#pragma unroll 2
        for (int r = myidx; r < cr; r += nsh) {
            const ulonglong2* wrow = (const ulonglong2*)(wb + r * ROWB);
            unsigned long long a0 = 0ull, a1 = 0ull;
#pragma unroll
            for (int j2 = 0; j2 < 16; j2++) {
                ulonglong2 w = wrow[j2];            // conflict-free broadcast
                fma2(a0, w.x, xr2[j2].x);
                fma2(a1, w.y, xr2[j2].y);
            }
            float2 f0 = u2f(a0), f1 = u2f(a1);
            float s = (f0.x + f0.y) + (f1.x + f1.y);
            s += __shfl_xor_sync(0xffffffffu, s, 4);    // fold 8 k-slices
            s += __shfl_xor_sync(0xffffffffu, s, 8);
            s += __shfl_xor_sync(0xffffffffu, s, 16);
            const int gr = c * CR + r;
            if (lane < 4 && valid)
                out[(size_t)my_tok * OUTW + colbase + gr] = s + __ldg(bias + gr);
        }
        __syncthreads();
        if (c + 2 < nc) { stage_chunk(sbase, W, c + 2, nrows, tid); }
        cpa_commit();
    }
}

__global__ __launch_bounds__(128, 4)
void decoder_kernel(const float* __restrict__ x,
                    const float* __restrict__ Wc,
                    const float* __restrict__ bc,
                    const float* __restrict__ Ww,
                    const float* __restrict__ bw,
                    const int* __restrict__ cls_raw,
                    float* __restrict__ out, int n) {
    __shared__ int s_tok[MAXTOK];
    __shared__ int s_cnt, s_not64;
    const int tid = threadIdx.x;
    const int warp = tid >> 5, lane = tid & 31;
    const int ks = lane >> 2, tq = lane & 3;
    const int bi = blockIdx.x;

    if (bi < NCLS) {
        // ----------------- words: one class per CTA -----------------
        const int c = bi;
        if (tid == 0) { s_cnt = 0; s_not64 = 0; }
        __syncthreads();
        // int32 vs int64 detection: odd int32 slots of int64 values in
        // [0,250) are all zero; int32 class values are not all zero.
        int flag = 0;
        for (int j = 2 * tid + 1; j < n; j += 256)
            if (cls_raw[j] != 0) flag = 1;
        if (flag) s_not64 = 1;
        __syncthreads();
        const int is64 = !s_not64;
        for (int i = tid; i < n; i += 128) {
            int cc = is64 ? cls_raw[2 * i] : cls_raw[i];
            if (cc == c) {
                int p = atomicAdd(&s_cnt, 1);
                if (p < MAXTOK) s_tok[p] = i;
            }
        }
        __syncthreads();
        const int cnt = min(s_cnt, MAXTOK);
        if (cnt == 0) return;

        const char* Wg = (const char*)Ww + (size_t)c * WROWS * NHID * 4;
        const float* biasw = bw + (size_t)c * WROWS;

        for (int base = 0; base < cnt; base += 16) {
            const int rem = cnt - base;
            const int G = min(4, (rem + 3) / 4);          // token quads
            const int myg = warp % G;
            const int nsh = 4 / G + (myg < (4 % G) ? 1 : 0);
            const int myidx = warp / G;
            const int tpos = base + myg * 4 + tq;
            const bool valid = tpos < cnt;
            const int my_tok = s_tok[valid ? tpos : (cnt - 1)];

            ulonglong2 xr2[16];
            const ulonglong2* xt = (const ulonglong2*)(
                x + (size_t)my_tok * NHID + ks * 64);
#pragma unroll
            for (int j2 = 0; j2 < 16; j2++) xr2[j2] = xt[j2];

            sweep(Wg, biasw, WROWS, NCLS, xr2, my_tok, valid, nsh, myidx,
                  out, tid, lane, ks);
        }
    } else {
        // ------------- cls: 16 tokens x half of Wc per CTA -------------
        const int q = bi - NCLS;
        const int gid = q >> 1;        // token group of 16
        const int h = q & 1;           // row half
        const int t0 = gid * 16;
        if (t0 >= n) return;
        const int rbase = h * 125;
        const int nrows = 125;

        const int tpos = t0 + warp * 4 + tq;
        const bool valid = tpos < n;
        const int my_tok = valid ? tpos : (n - 1);

        ulonglong2 xr2[16];
        const ulonglong2* xt = (const ulonglong2*)(
            x + (size_t)my_tok * NHID + ks * 64);
#pragma unroll
        for (int j2 = 0; j2 < 16; j2++) xr2[j2] = xt[j2];

        sweep((const char*)Wc + (size_t)rbase * NHID * 4, bc + rbase,
              nrows, rbase, xr2, my_tok, valid, /*nsh=*/1, /*myidx=*/0,
              out, tid, lane, ks);
    }
}

extern "C" void kernel_launch(void* const* d_in, const int* in_sizes, int n_in,
                              void* d_out, int out_size) {
    const float* x  = (const float*)d_in[0];
    const float* Wc = (const float*)d_in[1];
    const float* bc = (const float*)d_in[2];
    const float* Ww = (const float*)d_in[3];
    const float* bw = (const float*)d_in[4];
    const int*   ci = (const int*)d_in[5];
    const int n = in_sizes[0] / NHID;
    float* out = (float*)d_out;

    cudaFuncSetAttribute(decoder_kernel,
                         cudaFuncAttributeMaxDynamicSharedMemorySize, SMEM_DYN);
    const int cls_ctas = 2 * ((n + 15) / 16);
    const int grid = NCLS + cls_ctas;
    decoder_kernel<<<grid, 128, SMEM_DYN>>>(x, Wc, bc, Ww, bw, ci, out, n);
}